// round 16
// baseline (speedup 1.0000x reference)
#include <cuda_runtime.h>
#include <cuda_fp16.h>
#include <cuda_bf16.h>
#include <cstdint>

// ---------------- problem constants / scratch ----------------
#define NMAX 50000
#define EMAX 1600000
#define FEAT 256
#define NHEAD 4

__device__ __align__(16) __half g_h16[(long long)NMAX * FEAT];  // 25.6 MB fp16 h
__device__ __align__(16) __nv_bfloat16 g_xh[(long long)NMAX * FEAT];
__device__ __align__(16) __nv_bfloat16 g_xl[(long long)NMAX * FEAT];
__device__ __align__(16) __nv_bfloat16 g_wh[FEAT * FEAT];
__device__ __align__(16) __nv_bfloat16 g_wl[FEAT * FEAT];
__device__ __align__(16) float g_asrc[NMAX * NHEAD];
__device__ __align__(16) float g_adst[NMAX * NHEAD];
__device__ int   g_cnt[NMAX + 1];
__device__ int   g_off[NMAX + 2];
__device__ int   g_cur[NMAX + 1];
__device__ int   g_csr[EMAX + NMAX];

// ---------------- helpers ----------------
__device__ __forceinline__ uint32_t packbf(__nv_bfloat16 a, __nv_bfloat16 b) {
    __nv_bfloat162 t(a, b);
    return *(uint32_t*)&t;
}
__device__ __forceinline__ void bf16_split4(float4 v, uint2& hi, uint2& lo) {
    __nv_bfloat16 hx = __float2bfloat16_rn(v.x);
    __nv_bfloat16 hy = __float2bfloat16_rn(v.y);
    __nv_bfloat16 hz = __float2bfloat16_rn(v.z);
    __nv_bfloat16 hw = __float2bfloat16_rn(v.w);
    float lx = v.x - __bfloat162float(hx);
    float ly = v.y - __bfloat162float(hy);
    float lz = v.z - __bfloat162float(hz);
    float lw = v.w - __bfloat162float(hw);
    hi.x = packbf(hx, hy);
    hi.y = packbf(hz, hw);
    lo.x = packbf(__float2bfloat16_rn(lx), __float2bfloat16_rn(ly));
    lo.y = packbf(__float2bfloat16_rn(lz), __float2bfloat16_rn(lw));
}
__device__ __forceinline__ uint32_t smem_u32(const void* p) {
    return (uint32_t)__cvta_generic_to_shared(p);
}
__device__ __forceinline__ void ldsm_x4(uint32_t* r, uint32_t addr) {
    asm volatile("ldmatrix.sync.aligned.m8n8.x4.shared.b16 {%0,%1,%2,%3}, [%4];"
                 : "=r"(r[0]), "=r"(r[1]), "=r"(r[2]), "=r"(r[3]) : "r"(addr));
}
__device__ __forceinline__ void ldsm_x4_trans(uint32_t* r, uint32_t addr) {
    asm volatile("ldmatrix.sync.aligned.m8n8.x4.trans.shared.b16 {%0,%1,%2,%3}, [%4];"
                 : "=r"(r[0]), "=r"(r[1]), "=r"(r[2]), "=r"(r[3]) : "r"(addr));
}
__device__ __forceinline__ void mma16(float* d, const uint32_t* a, uint32_t b0, uint32_t b1) {
    asm volatile("mma.sync.aligned.m16n8k16.row.col.f32.bf16.bf16.f32 "
                 "{%0,%1,%2,%3}, {%4,%5,%6,%7}, {%8,%9}, {%0,%1,%2,%3};"
                 : "+f"(d[0]), "+f"(d[1]), "+f"(d[2]), "+f"(d[3])
                 : "r"(a[0]), "r"(a[1]), "r"(a[2]), "r"(a[3]), "r"(b0), "r"(b1));
}
__device__ __forceinline__ void cp16(uint32_t dst, const void* src, uint32_t sz) {
    asm volatile("cp.async.cg.shared.global [%0], [%1], 16, %2;"
                 :: "r"(dst), "l"(src), "r"(sz));
}
#define CP_COMMIT() asm volatile("cp.async.commit_group;")
#define CP_WAIT(n)  asm volatile("cp.async.wait_group %0;" :: "n"(n))

// ---------------- 0: zero counters ----------------
__global__ void zero_kernel(int N) {
    int i = blockIdx.x * blockDim.x + threadIdx.x;
    if (i <= N) g_cnt[i] = 0;
}

// ---------------- 0b: bf16 split pre-pass ----------------
__global__ void split_x_kernel(const float* __restrict__ src, int n4) {
    int i = blockIdx.x * blockDim.x + threadIdx.x;
    if (i >= n4) return;
    float4 v = ((const float4*)src)[i];
    uint2 hi, lo;
    bf16_split4(v, hi, lo);
    ((uint2*)g_xh)[i] = hi;
    ((uint2*)g_xl)[i] = lo;
}
__global__ void split_w_kernel(const float* __restrict__ src, int n4) {
    int i = blockIdx.x * blockDim.x + threadIdx.x;
    if (i >= n4) return;
    float4 v = ((const float4*)src)[i];
    uint2 hi, lo;
    bf16_split4(v, hi, lo);
    ((uint2*)g_wh)[i] = hi;
    ((uint2*)g_wl)[i] = lo;
}

// ---------------- 1: bf16 split-3 MMA GEMM (cp.async) + fused logits + h16 ----------------
#define LDAg 40
#define LDBg 136
#define A_PLANE (128 * LDAg)
#define B_PLANE (32 * LDBg)
#define STAGE_ELEMS (2 * A_PLANE + 2 * B_PLANE)
#define GEMM_SMEM_BYTES (2 * STAGE_ELEMS * 2)     // 75776 B

__global__ void __launch_bounds__(256, 2)
gemm_bf16_kernel(const float* __restrict__ att_src, const float* __restrict__ att_dst,
                 int M) {
    extern __shared__ __nv_bfloat16 S[];
    const int tid = threadIdx.x;
    const int wid = tid >> 5, lane = tid & 31;
    const int warp_m = wid & 3;
    const int warp_n = wid >> 2;
    const int gid = lane >> 2, tig = lane & 3;
    const int lr = lane & 15;
    const int lc8 = (lane >> 4) * 8;
    const int row0 = blockIdx.y * 128;
    const int col0 = blockIdx.x * 128;
    const uint32_t sbase = smem_u32(S);

    float acc[2][8][4];
#pragma unroll
    for (int i = 0; i < 2; i++)
#pragma unroll
        for (int j = 0; j < 8; j++)
#pragma unroll
            for (int q = 0; q < 4; q++) acc[i][j][q] = 0.f;

    auto stage_load = [&](int c, int stage) {
        const int k0 = c * 32;
        const uint32_t sb = sbase + (uint32_t)stage * (STAGE_ELEMS * 2);
#pragma unroll
        for (int u = 0; u < 2; u++) {
            int chunk = tid + u * 256;
            int rA = chunk >> 2, cA = (chunk & 3) * 8;
            uint32_t dA = sb + 2 * (uint32_t)(rA * LDAg + cA);
            uint32_t szA = (row0 + rA < M) ? 16u : 0u;
            size_t offA = (size_t)(row0 + rA) * 256 + k0 + cA;
            cp16(dA,               &g_xh[offA], szA);
            cp16(dA + A_PLANE * 2, &g_xl[offA], szA);
            int rB = chunk >> 4, cB = (chunk & 15) * 8;
            uint32_t dB = sb + (2 * A_PLANE) * 2 + 2 * (uint32_t)(rB * LDBg + cB);
            size_t offB = (size_t)(k0 + rB) * 256 + col0 + cB;
            cp16(dB,               &g_wh[offB], 16u);
            cp16(dB + B_PLANE * 2, &g_wl[offB], 16u);
        }
    };

    stage_load(0, 0);
    CP_COMMIT();

    for (int c = 0; c < 8; c++) {
        if (c < 7) {
            stage_load(c + 1, (c + 1) & 1);
            CP_COMMIT();
            CP_WAIT(1);
        } else {
            CP_WAIT(0);
        }
        __syncthreads();

        {
            const uint32_t stOff = (uint32_t)((c & 1) * STAGE_ELEMS);
#pragma unroll
            for (int ks = 0; ks < 2; ks++) {
                const int k16 = ks * 16;
                uint32_t ah[2][4], al[2][4];
#pragma unroll
                for (int i = 0; i < 2; i++) {
                    uint32_t aoff = stOff + (uint32_t)(warp_m * 32 + i * 16 + lr) * LDAg + k16 + lc8;
                    ldsm_x4(ah[i], sbase + 2 * aoff);
                    ldsm_x4(al[i], sbase + 2 * (aoff + A_PLANE));
                }
#pragma unroll
                for (int j = 0; j < 8; j += 2) {
                    uint32_t boff = stOff + 2 * A_PLANE +
                                    (uint32_t)(k16 + lr) * LDBg + warp_n * 64 + j * 8 + lc8;
                    uint32_t bh[4], bl[4];
                    ldsm_x4_trans(bh, sbase + 2 * boff);
                    ldsm_x4_trans(bl, sbase + 2 * (boff + B_PLANE));
#pragma unroll
                    for (int i = 0; i < 2; i++) {
                        mma16(acc[i][j],     al[i], bh[0], bh[1]);
                        mma16(acc[i][j],     ah[i], bl[0], bl[1]);
                        mma16(acc[i][j],     ah[i], bh[0], bh[1]);
                        mma16(acc[i][j + 1], al[i], bh[2], bh[3]);
                        mma16(acc[i][j + 1], ah[i], bl[2], bl[3]);
                        mma16(acc[i][j + 1], ah[i], bh[2], bh[3]);
                    }
                }
            }
        }
        __syncthreads();
    }

    // ---- epilogue A: h16 store ----
#pragma unroll
    for (int i = 0; i < 2; i++) {
        int r0 = row0 + warp_m * 32 + i * 16 + gid;
#pragma unroll
        for (int j = 0; j < 8; j++) {
            int cc = col0 + warp_n * 64 + j * 8 + tig * 2;
            if (r0 < M)
                *(__half2*)&g_h16[(size_t)r0 * 256 + cc] =
                    __floats2half2_rn(acc[i][j][0], acc[i][j][1]);
            if (r0 + 8 < M)
                *(__half2*)&g_h16[(size_t)(r0 + 8) * 256 + cc] =
                    __floats2half2_rn(acc[i][j][2], acc[i][j][3]);
        }
    }

    // ---- epilogue B: fused attention logits ----
    const int head = blockIdx.x * 2 + warp_n;
#pragma unroll
    for (int i = 0; i < 2; i++) {
        float a0 = 0.f, a8 = 0.f, d0 = 0.f, d8 = 0.f;
#pragma unroll
        for (int j = 0; j < 8; j++) {
            int cc = col0 + warp_n * 64 + j * 8 + tig * 2;
            float w0 = att_src[cc], w1 = att_src[cc + 1];
            float u0 = att_dst[cc], u1 = att_dst[cc + 1];
            a0 += acc[i][j][0] * w0 + acc[i][j][1] * w1;
            a8 += acc[i][j][2] * w0 + acc[i][j][3] * w1;
            d0 += acc[i][j][0] * u0 + acc[i][j][1] * u1;
            d8 += acc[i][j][2] * u0 + acc[i][j][3] * u1;
        }
#pragma unroll
        for (int st = 1; st <= 2; st <<= 1) {
            a0 += __shfl_xor_sync(0xffffffff, a0, st);
            a8 += __shfl_xor_sync(0xffffffff, a8, st);
            d0 += __shfl_xor_sync(0xffffffff, d0, st);
            d8 += __shfl_xor_sync(0xffffffff, d8, st);
        }
        if (tig == 0) {
            int r = row0 + warp_m * 32 + i * 16 + gid;
            if (r < M)     { g_asrc[r * 4 + head] = a0; g_adst[r * 4 + head] = d0; }
            if (r + 8 < M) { g_asrc[(r + 8) * 4 + head] = a8; g_adst[(r + 8) * 4 + head] = d8; }
        }
    }
}

// ---------------- 3: dst histogram ----------------
__global__ void count_kernel(const int* __restrict__ ei, int E, int N) {
    int i = blockIdx.x * blockDim.x + threadIdx.x;
    if (i >= E + N) return;
    int dst = (i < E) ? ei[E + i] : (i - E);
    atomicAdd(&g_cnt[dst], 1);
}

// ---------------- 4: single-block exclusive scan ----------------
__global__ void scan_kernel(int N) {
    __shared__ int sm[1024];
    __shared__ int carry;
    const int tid = threadIdx.x;
    if (tid == 0) carry = 0;
    __syncthreads();
    for (int base = 0; base < N; base += 1024) {
        int i = base + tid;
        int v = (i < N) ? g_cnt[i] : 0;
        sm[tid] = v;
        __syncthreads();
        for (int s = 1; s < 1024; s <<= 1) {
            int t = (tid >= s) ? sm[tid - s] : 0;
            __syncthreads();
            sm[tid] += t;
            __syncthreads();
        }
        int excl = sm[tid] - v + carry;
        if (i < N) { g_off[i] = excl; g_cur[i] = excl; }
        __syncthreads();
        if (tid == 1023) carry += sm[1023];
        __syncthreads();
    }
    if (tid == 0) g_off[N] = carry;
}

// ---------------- 5: scatter edges (CSR only) ----------------
__global__ void scatter_kernel(const int* __restrict__ ei, int E, int N) {
    int i = blockIdx.x * blockDim.x + threadIdx.x;
    if (i >= E + N) return;
    int src, dst;
    if (i < E) { src = ei[i]; dst = ei[E + i]; }
    else       { src = dst = i - E; }
    int slot = atomicAdd(&g_cur[dst], 1);
    g_csr[slot] = src;
}

// ---------------- 7: warp-per-dst gather, MLP-8, 64-thread blocks ----------------
__global__ void __launch_bounds__(64)
aggregate_kernel(const float* __restrict__ bias, float* __restrict__ out, int N) {
    const int w    = (blockIdx.x * blockDim.x + threadIdx.x) >> 5;
    const int lane = threadIdx.x & 31;
    if (w >= N) return;
    const int c0   = lane * 8;
    const int head = lane >> 3;

    const int beg = g_off[w];
    const int end = g_off[w + 1];
    const float adh = g_adst[w * NHEAD + head];

    float den = 0.f;
    float4 accA = make_float4(0.f, 0.f, 0.f, 0.f);
    float4 accB = make_float4(0.f, 0.f, 0.f, 0.f);

    int i = beg;
    for (; i + 7 < end; i += 8) {
        int s[8];
#pragma unroll
        for (int k = 0; k < 8; k++) s[k] = g_csr[i + k];
        float e[8];
#pragma unroll
        for (int k = 0; k < 8; k++) e[k] = g_asrc[s[k] * NHEAD + head];
        uint4 h[8];
#pragma unroll
        for (int k = 0; k < 8; k++) h[k] = *(const uint4*)&g_h16[s[k] * FEAT + c0];
#pragma unroll
        for (int k = 0; k < 8; k++) {
            float ek = e[k] + adh;
            ek = ek >= 0.f ? ek : 0.2f * ek;
            float a = __expf(ek);
            den += a;
            float2 f0 = __half22float2(*(__half2*)&h[k].x);
            float2 f1 = __half22float2(*(__half2*)&h[k].y);
            float2 f2 = __half22float2(*(__half2*)&h[k].z);
            float2 f3 = __half22float2(*(__half2*)&h[k].w);
            accA.x += f0.x * a; accA.y += f0.y * a;
            accA.z += f1.x * a; accA.w += f1.y * a;
            accB.x += f2.x * a; accB.y += f2.y * a;
            accB.z += f3.x * a; accB.w += f3.y * a;
        }
    }
    for (; i + 3 < end; i += 4) {
        int s[4];
#pragma unroll
        for (int k = 0; k < 4; k++) s[k] = g_csr[i + k];
        float e[4];
#pragma unroll
        for (int k = 0; k < 4; k++) e[k] = g_asrc[s[k] * NHEAD + head];
        uint4 h[4];
#pragma unroll
        for (int k = 0; k < 4; k++) h[k] = *(const uint4*)&g_h16[s[k] * FEAT + c0];
#pragma unroll
        for (int k = 0; k < 4; k++) {
            float ek = e[k] + adh;
            ek = ek >= 0.f ? ek : 0.2f * ek;
            float a = __expf(ek);
            den += a;
            float2 f0 = __half22float2(*(__half2*)&h[k].x);
            float2 f1 = __half22float2(*(__half2*)&h[k].y);
            float2 f2 = __half22float2(*(__half2*)&h[k].z);
            float2 f3 = __half22float2(*(__half2*)&h[k].w);
            accA.x += f0.x * a; accA.y += f0.y * a;
            accA.z += f1.x * a; accA.w += f1.y * a;
            accB.x += f2.x * a; accB.y += f2.y * a;
            accB.z += f3.x * a; accB.w += f3.y * a;
        }
    }
    for (; i < end; i++) {
        int s = g_csr[i];
        float e = g_asrc[s * NHEAD + head] + adh;
        e = e >= 0.f ? e : 0.2f * e;
        float a = __expf(e);
        den += a;
        uint4 hv = *(const uint4*)&g_h16[s * FEAT + c0];
        float2 f0 = __half22float2(*(__half2*)&hv.x);
        float2 f1 = __half22float2(*(__half2*)&hv.y);
        float2 f2 = __half22float2(*(__half2*)&hv.z);
        float2 f3 = __half22float2(*(__half2*)&hv.w);
        accA.x += f0.x * a; accA.y += f0.y * a;
        accA.z += f1.x * a; accA.w += f1.y * a;
        accB.x += f2.x * a; accB.y += f2.y * a;
        accB.z += f3.x * a; accB.w += f3.y * a;
    }

    float inv = 1.f / den;
    float4 bA = *(const float4*)&bias[c0];
    float4 bB = *(const float4*)&bias[c0 + 4];
    accA.x = fmaxf(accA.x * inv + bA.x, 0.f); accA.y = fmaxf(accA.y * inv + bA.y, 0.f);
    accA.z = fmaxf(accA.z * inv + bA.z, 0.f); accA.w = fmaxf(accA.w * inv + bA.w, 0.f);
    accB.x = fmaxf(accB.x * inv + bB.x, 0.f); accB.y = fmaxf(accB.y * inv + bB.y, 0.f);
    accB.z = fmaxf(accB.z * inv + bB.z, 0.f); accB.w = fmaxf(accB.w * inv + bB.w, 0.f);
    float sq = accA.x * accA.x + accA.y * accA.y + accA.z * accA.z + accA.w * accA.w
             + accB.x * accB.x + accB.y * accB.y + accB.z * accB.z + accB.w * accB.w;
#pragma unroll
    for (int st = 16; st >= 1; st >>= 1)
        sq += __shfl_xor_sync(0xffffffff, sq, st);
    float sc = 1.f / fmaxf(sqrtf(sq), 1e-12f);
    accA.x *= sc; accA.y *= sc; accA.z *= sc; accA.w *= sc;
    accB.x *= sc; accB.y *= sc; accB.z *= sc; accB.w *= sc;
    *(float4*)&out[w * FEAT + c0]     = accA;
    *(float4*)&out[w * FEAT + c0 + 4] = accB;
}

// ---------------- launch: fork-join over two streams ----------------
static cudaStream_t g_s2 = nullptr;
static cudaEvent_t  g_eStart = nullptr, g_eEdges = nullptr;
static bool g_streams_ok = false;

extern "C" void kernel_launch(void* const* d_in, const int* in_sizes, int n_in,
                              void* d_out, int out_size) {
    const float* x       = (const float*)d_in[0];
    const int*   ei      = (const int*)  d_in[1];
    const float* W       = (const float*)d_in[2];
    const float* att_src = (const float*)d_in[3];
    const float* att_dst = (const float*)d_in[4];
    const float* bias    = (const float*)d_in[5];
    float* out = (float*)d_out;

    const int N = in_sizes[0] / FEAT;
    const int E = in_sizes[1] / 2;
    const int tot = E + N;

    static bool init_done = false;
    if (!init_done) {
        cudaFuncSetAttribute(gemm_bf16_kernel,
                             cudaFuncAttributeMaxDynamicSharedMemorySize, GEMM_SMEM_BYTES);
        bool ok = (cudaStreamCreateWithFlags(&g_s2, cudaStreamNonBlocking) == cudaSuccess);
        ok = ok && (cudaEventCreateWithFlags(&g_eStart, cudaEventDisableTiming) == cudaSuccess);
        ok = ok && (cudaEventCreateWithFlags(&g_eEdges, cudaEventDisableTiming) == cudaSuccess);
        g_streams_ok = ok;
        init_done = true;
    }

    dim3 ggrid(FEAT / 128, (N + 127) / 128);

    if (g_streams_ok) {
        zero_kernel<<<(N + 256) / 256, 256>>>(N);
        cudaEventRecord(g_eStart, 0);

        // chain B on stream 0 (gemm = issue index 3, profiled control)
        split_x_kernel<<<(N * 64 + 255) / 256, 256>>>(x, N * 64);
        split_w_kernel<<<(FEAT * FEAT / 4 + 255) / 256, 256>>>(W, FEAT * FEAT / 4);
        gemm_bf16_kernel<<<ggrid, 256, GEMM_SMEM_BYTES>>>(att_src, att_dst, N);

        // chain A on s2
        cudaStreamWaitEvent(g_s2, g_eStart, 0);
        count_kernel<<<(tot + 255) / 256, 256, 0, g_s2>>>(ei, E, N);
        scan_kernel<<<1, 1024, 0, g_s2>>>(N);
        scatter_kernel<<<(tot + 255) / 256, 256, 0, g_s2>>>(ei, E, N);
        cudaEventRecord(g_eEdges, g_s2);

        cudaStreamWaitEvent(0, g_eEdges, 0);
        aggregate_kernel<<<(N * 32 + 63) / 64, 64>>>(bias, out, N);
    } else {
        zero_kernel<<<(N + 256) / 256, 256>>>(N);
        split_x_kernel<<<(N * 64 + 255) / 256, 256>>>(x, N * 64);
        split_w_kernel<<<(FEAT * FEAT / 4 + 255) / 256, 256>>>(W, FEAT * FEAT / 4);
        gemm_bf16_kernel<<<ggrid, 256, GEMM_SMEM_BYTES>>>(att_src, att_dst, N);
        count_kernel<<<(tot + 255) / 256, 256>>>(ei, E, N);
        scan_kernel<<<1, 1024>>>(N);
        scatter_kernel<<<(tot + 255) / 256, 256>>>(ei, E, N);
        aggregate_kernel<<<(N * 32 + 63) / 64, 64>>>(bias, out, N);
    }
}

// round 17
// speedup vs baseline: 1.3469x; 1.3469x over previous
#include <cuda_runtime.h>
#include <cuda_fp16.h>
#include <cuda_bf16.h>
#include <cstdint>

// ---------------- problem constants / scratch ----------------
#define NMAX 50000
#define EMAX 1600000
#define FEAT 256
#define NHEAD 4

__device__ __align__(16) __half g_h16[(long long)NMAX * FEAT];  // 25.6 MB fp16 h
__device__ __align__(16) __nv_bfloat16 g_xh[(long long)NMAX * FEAT];
__device__ __align__(16) __nv_bfloat16 g_xl[(long long)NMAX * FEAT];
__device__ __align__(16) __nv_bfloat16 g_wh[FEAT * FEAT];
__device__ __align__(16) __nv_bfloat16 g_wl[FEAT * FEAT];
__device__ __align__(16) float g_asrc[NMAX * NHEAD];
__device__ __align__(16) float g_adst[NMAX * NHEAD];
__device__ int   g_cnt[NMAX + 1];
__device__ int   g_off[NMAX + 2];
__device__ int   g_cur[NMAX + 1];
__device__ int   g_csr[EMAX + NMAX];
__device__ int   g_bsum[64];
__device__ int   g_bscan[64];

// ---------------- helpers ----------------
__device__ __forceinline__ uint32_t packbf(__nv_bfloat16 a, __nv_bfloat16 b) {
    __nv_bfloat162 t(a, b);
    return *(uint32_t*)&t;
}
__device__ __forceinline__ void bf16_split4(float4 v, uint2& hi, uint2& lo) {
    __nv_bfloat16 hx = __float2bfloat16_rn(v.x);
    __nv_bfloat16 hy = __float2bfloat16_rn(v.y);
    __nv_bfloat16 hz = __float2bfloat16_rn(v.z);
    __nv_bfloat16 hw = __float2bfloat16_rn(v.w);
    float lx = v.x - __bfloat162float(hx);
    float ly = v.y - __bfloat162float(hy);
    float lz = v.z - __bfloat162float(hz);
    float lw = v.w - __bfloat162float(hw);
    hi.x = packbf(hx, hy);
    hi.y = packbf(hz, hw);
    lo.x = packbf(__float2bfloat16_rn(lx), __float2bfloat16_rn(ly));
    lo.y = packbf(__float2bfloat16_rn(lz), __float2bfloat16_rn(lw));
}
__device__ __forceinline__ uint32_t smem_u32(const void* p) {
    return (uint32_t)__cvta_generic_to_shared(p);
}
__device__ __forceinline__ void ldsm_x4(uint32_t* r, uint32_t addr) {
    asm volatile("ldmatrix.sync.aligned.m8n8.x4.shared.b16 {%0,%1,%2,%3}, [%4];"
                 : "=r"(r[0]), "=r"(r[1]), "=r"(r[2]), "=r"(r[3]) : "r"(addr));
}
__device__ __forceinline__ void ldsm_x4_trans(uint32_t* r, uint32_t addr) {
    asm volatile("ldmatrix.sync.aligned.m8n8.x4.trans.shared.b16 {%0,%1,%2,%3}, [%4];"
                 : "=r"(r[0]), "=r"(r[1]), "=r"(r[2]), "=r"(r[3]) : "r"(addr));
}
__device__ __forceinline__ void mma16(float* d, const uint32_t* a, uint32_t b0, uint32_t b1) {
    asm volatile("mma.sync.aligned.m16n8k16.row.col.f32.bf16.bf16.f32 "
                 "{%0,%1,%2,%3}, {%4,%5,%6,%7}, {%8,%9}, {%0,%1,%2,%3};"
                 : "+f"(d[0]), "+f"(d[1]), "+f"(d[2]), "+f"(d[3])
                 : "r"(a[0]), "r"(a[1]), "r"(a[2]), "r"(a[3]), "r"(b0), "r"(b1));
}
__device__ __forceinline__ void cp16(uint32_t dst, const void* src, uint32_t sz) {
    asm volatile("cp.async.cg.shared.global [%0], [%1], 16, %2;"
                 :: "r"(dst), "l"(src), "r"(sz));
}
#define CP_COMMIT() asm volatile("cp.async.commit_group;")
#define CP_WAIT(n)  asm volatile("cp.async.wait_group %0;" :: "n"(n))

// ---------------- 0: zero counters ----------------
__global__ void zero_kernel(int N) {
    int i = blockIdx.x * blockDim.x + threadIdx.x;
    if (i <= N) g_cnt[i] = 0;
}

// ---------------- 0b: bf16 split pre-pass ----------------
__global__ void split_x_kernel(const float* __restrict__ src, int n4) {
    int i = blockIdx.x * blockDim.x + threadIdx.x;
    if (i >= n4) return;
    float4 v = ((const float4*)src)[i];
    uint2 hi, lo;
    bf16_split4(v, hi, lo);
    ((uint2*)g_xh)[i] = hi;
    ((uint2*)g_xl)[i] = lo;
}
__global__ void split_w_kernel(const float* __restrict__ src, int n4) {
    int i = blockIdx.x * blockDim.x + threadIdx.x;
    if (i >= n4) return;
    float4 v = ((const float4*)src)[i];
    uint2 hi, lo;
    bf16_split4(v, hi, lo);
    ((uint2*)g_wh)[i] = hi;
    ((uint2*)g_wl)[i] = lo;
}

// ---------------- 1: bf16 split-3 MMA GEMM (cp.async) + fused logits + h16 ----------------
#define LDAg 40
#define LDBg 136
#define A_PLANE (128 * LDAg)
#define B_PLANE (32 * LDBg)
#define STAGE_ELEMS (2 * A_PLANE + 2 * B_PLANE)
#define GEMM_SMEM_BYTES (2 * STAGE_ELEMS * 2)     // 75776 B

__global__ void __launch_bounds__(256, 2)
gemm_bf16_kernel(const float* __restrict__ att_src, const float* __restrict__ att_dst,
                 int M) {
    extern __shared__ __nv_bfloat16 S[];
    const int tid = threadIdx.x;
    const int wid = tid >> 5, lane = tid & 31;
    const int warp_m = wid & 3;
    const int warp_n = wid >> 2;
    const int gid = lane >> 2, tig = lane & 3;
    const int lr = lane & 15;
    const int lc8 = (lane >> 4) * 8;
    const int row0 = blockIdx.y * 128;
    const int col0 = blockIdx.x * 128;
    const uint32_t sbase = smem_u32(S);

    float acc[2][8][4];
#pragma unroll
    for (int i = 0; i < 2; i++)
#pragma unroll
        for (int j = 0; j < 8; j++)
#pragma unroll
            for (int q = 0; q < 4; q++) acc[i][j][q] = 0.f;

    auto stage_load = [&](int c, int stage) {
        const int k0 = c * 32;
        const uint32_t sb = sbase + (uint32_t)stage * (STAGE_ELEMS * 2);
#pragma unroll
        for (int u = 0; u < 2; u++) {
            int chunk = tid + u * 256;
            int rA = chunk >> 2, cA = (chunk & 3) * 8;
            uint32_t dA = sb + 2 * (uint32_t)(rA * LDAg + cA);
            uint32_t szA = (row0 + rA < M) ? 16u : 0u;
            size_t offA = (size_t)(row0 + rA) * 256 + k0 + cA;
            cp16(dA,               &g_xh[offA], szA);
            cp16(dA + A_PLANE * 2, &g_xl[offA], szA);
            int rB = chunk >> 4, cB = (chunk & 15) * 8;
            uint32_t dB = sb + (2 * A_PLANE) * 2 + 2 * (uint32_t)(rB * LDBg + cB);
            size_t offB = (size_t)(k0 + rB) * 256 + col0 + cB;
            cp16(dB,               &g_wh[offB], 16u);
            cp16(dB + B_PLANE * 2, &g_wl[offB], 16u);
        }
    };

    stage_load(0, 0);
    CP_COMMIT();

    for (int c = 0; c < 8; c++) {
        if (c < 7) {
            stage_load(c + 1, (c + 1) & 1);
            CP_COMMIT();
            CP_WAIT(1);
        } else {
            CP_WAIT(0);
        }
        __syncthreads();

        {
            const uint32_t stOff = (uint32_t)((c & 1) * STAGE_ELEMS);
#pragma unroll
            for (int ks = 0; ks < 2; ks++) {
                const int k16 = ks * 16;
                uint32_t ah[2][4], al[2][4];
#pragma unroll
                for (int i = 0; i < 2; i++) {
                    uint32_t aoff = stOff + (uint32_t)(warp_m * 32 + i * 16 + lr) * LDAg + k16 + lc8;
                    ldsm_x4(ah[i], sbase + 2 * aoff);
                    ldsm_x4(al[i], sbase + 2 * (aoff + A_PLANE));
                }
#pragma unroll
                for (int j = 0; j < 8; j += 2) {
                    uint32_t boff = stOff + 2 * A_PLANE +
                                    (uint32_t)(k16 + lr) * LDBg + warp_n * 64 + j * 8 + lc8;
                    uint32_t bh[4], bl[4];
                    ldsm_x4_trans(bh, sbase + 2 * boff);
                    ldsm_x4_trans(bl, sbase + 2 * (boff + B_PLANE));
#pragma unroll
                    for (int i = 0; i < 2; i++) {
                        mma16(acc[i][j],     al[i], bh[0], bh[1]);
                        mma16(acc[i][j],     ah[i], bl[0], bl[1]);
                        mma16(acc[i][j],     ah[i], bh[0], bh[1]);
                        mma16(acc[i][j + 1], al[i], bh[2], bh[3]);
                        mma16(acc[i][j + 1], ah[i], bl[2], bl[3]);
                        mma16(acc[i][j + 1], ah[i], bh[2], bh[3]);
                    }
                }
            }
        }
        __syncthreads();
    }

    // ---- epilogue A: h16 store ----
#pragma unroll
    for (int i = 0; i < 2; i++) {
        int r0 = row0 + warp_m * 32 + i * 16 + gid;
#pragma unroll
        for (int j = 0; j < 8; j++) {
            int cc = col0 + warp_n * 64 + j * 8 + tig * 2;
            if (r0 < M)
                *(__half2*)&g_h16[(size_t)r0 * 256 + cc] =
                    __floats2half2_rn(acc[i][j][0], acc[i][j][1]);
            if (r0 + 8 < M)
                *(__half2*)&g_h16[(size_t)(r0 + 8) * 256 + cc] =
                    __floats2half2_rn(acc[i][j][2], acc[i][j][3]);
        }
    }

    // ---- epilogue B: fused attention logits ----
    const int head = blockIdx.x * 2 + warp_n;
#pragma unroll
    for (int i = 0; i < 2; i++) {
        float a0 = 0.f, a8 = 0.f, d0 = 0.f, d8 = 0.f;
#pragma unroll
        for (int j = 0; j < 8; j++) {
            int cc = col0 + warp_n * 64 + j * 8 + tig * 2;
            float w0 = att_src[cc], w1 = att_src[cc + 1];
            float u0 = att_dst[cc], u1 = att_dst[cc + 1];
            a0 += acc[i][j][0] * w0 + acc[i][j][1] * w1;
            a8 += acc[i][j][2] * w0 + acc[i][j][3] * w1;
            d0 += acc[i][j][0] * u0 + acc[i][j][1] * u1;
            d8 += acc[i][j][2] * u0 + acc[i][j][3] * u1;
        }
#pragma unroll
        for (int st = 1; st <= 2; st <<= 1) {
            a0 += __shfl_xor_sync(0xffffffff, a0, st);
            a8 += __shfl_xor_sync(0xffffffff, a8, st);
            d0 += __shfl_xor_sync(0xffffffff, d0, st);
            d8 += __shfl_xor_sync(0xffffffff, d8, st);
        }
        if (tig == 0) {
            int r = row0 + warp_m * 32 + i * 16 + gid;
            if (r < M)     { g_asrc[r * 4 + head] = a0; g_adst[r * 4 + head] = d0; }
            if (r + 8 < M) { g_asrc[(r + 8) * 4 + head] = a8; g_adst[(r + 8) * 4 + head] = d8; }
        }
    }
}

// ---------------- 3: dst histogram ----------------
__global__ void count_kernel(const int* __restrict__ ei, int E, int N) {
    int i = blockIdx.x * blockDim.x + threadIdx.x;
    if (i >= E + N) return;
    int dst = (i < E) ? ei[E + i] : (i - E);
    atomicAdd(&g_cnt[dst], 1);
}

// ---------------- 4: three-phase parallel exclusive scan ----------------
// phase 1: per-block (1024 elems) exclusive scan + block sums
__global__ void scan1_kernel(int N) {
    __shared__ int wsum[8];
    const int b = blockIdx.x, tid = threadIdx.x;
    const int lane = tid & 31, wid = tid >> 5;
    const int base = b * 1024 + tid * 4;
    int v[4];
#pragma unroll
    for (int k = 0; k < 4; k++) v[k] = (base + k < N) ? g_cnt[base + k] : 0;
    int t = v[0] + v[1] + v[2] + v[3];
    int inc = t;
#pragma unroll
    for (int d = 1; d < 32; d <<= 1) {
        int n = __shfl_up_sync(0xffffffff, inc, d);
        if (lane >= d) inc += n;
    }
    if (lane == 31) wsum[wid] = inc;
    __syncthreads();
    if (wid == 0) {
        int ws = (lane < 8) ? wsum[lane] : 0;
#pragma unroll
        for (int d = 1; d < 8; d <<= 1) {
            int n = __shfl_up_sync(0xffffffff, ws, d);
            if (lane >= d) ws += n;
        }
        if (lane < 8) wsum[lane] = ws;       // inclusive warp prefix
        if (lane == 7) g_bsum[b] = ws;       // block total
    }
    __syncthreads();
    int run = inc - t + (wid > 0 ? wsum[wid - 1] : 0);
#pragma unroll
    for (int k = 0; k < 4; k++) {
        if (base + k < N) g_off[base + k] = run;
        run += v[k];
    }
}
// phase 2: scan the (<=64) block sums; also writes g_off[N] = total
__global__ void scan2_kernel(int nb, int N) {
    __shared__ int s[64];
    int lane = threadIdx.x;   // 64 threads
    int v = (lane < nb) ? g_bsum[lane] : 0;
    s[lane] = v;
    __syncthreads();
    for (int d = 1; d < 64; d <<= 1) {
        int t = (lane >= d) ? s[lane - d] : 0;
        __syncthreads();
        s[lane] += t;
        __syncthreads();
    }
    g_bscan[lane] = s[lane] - v;             // exclusive
    if (lane == 63) g_off[N] = s[63];
}
// phase 3: add block offsets, materialize g_cur
__global__ void scan3_kernel(int N) {
    const int b = blockIdx.x, tid = threadIdx.x;
    const int base = b * 1024 + tid * 4;
    const int off = g_bscan[b];
#pragma unroll
    for (int k = 0; k < 4; k++) {
        int i = base + k;
        if (i < N) {
            int o = g_off[i] + off;
            g_off[i] = o;
            g_cur[i] = o;
        }
    }
}

// ---------------- 5: scatter edges (CSR only) ----------------
__global__ void scatter_kernel(const int* __restrict__ ei, int E, int N) {
    int i = blockIdx.x * blockDim.x + threadIdx.x;
    if (i >= E + N) return;
    int src, dst;
    if (i < E) { src = ei[i]; dst = ei[E + i]; }
    else       { src = dst = i - E; }
    int slot = atomicAdd(&g_cur[dst], 1);
    g_csr[slot] = src;
}

// ---------------- 7: warp-per-dst gather, MLP-8, 64-thread blocks ----------------
__global__ void __launch_bounds__(64)
aggregate_kernel(const float* __restrict__ bias, float* __restrict__ out, int N) {
    const int w    = (blockIdx.x * blockDim.x + threadIdx.x) >> 5;
    const int lane = threadIdx.x & 31;
    if (w >= N) return;
    const int c0   = lane * 8;
    const int head = lane >> 3;

    const int beg = g_off[w];
    const int end = g_off[w + 1];
    const float adh = g_adst[w * NHEAD + head];

    float den = 0.f;
    float4 accA = make_float4(0.f, 0.f, 0.f, 0.f);
    float4 accB = make_float4(0.f, 0.f, 0.f, 0.f);

    int i = beg;
    for (; i + 7 < end; i += 8) {
        int s[8];
#pragma unroll
        for (int k = 0; k < 8; k++) s[k] = g_csr[i + k];
        float e[8];
#pragma unroll
        for (int k = 0; k < 8; k++) e[k] = g_asrc[s[k] * NHEAD + head];
        uint4 h[8];
#pragma unroll
        for (int k = 0; k < 8; k++) h[k] = *(const uint4*)&g_h16[s[k] * FEAT + c0];
#pragma unroll
        for (int k = 0; k < 8; k++) {
            float ek = e[k] + adh;
            ek = ek >= 0.f ? ek : 0.2f * ek;
            float a = __expf(ek);
            den += a;
            float2 f0 = __half22float2(*(__half2*)&h[k].x);
            float2 f1 = __half22float2(*(__half2*)&h[k].y);
            float2 f2 = __half22float2(*(__half2*)&h[k].z);
            float2 f3 = __half22float2(*(__half2*)&h[k].w);
            accA.x += f0.x * a; accA.y += f0.y * a;
            accA.z += f1.x * a; accA.w += f1.y * a;
            accB.x += f2.x * a; accB.y += f2.y * a;
            accB.z += f3.x * a; accB.w += f3.y * a;
        }
    }
    for (; i + 3 < end; i += 4) {
        int s[4];
#pragma unroll
        for (int k = 0; k < 4; k++) s[k] = g_csr[i + k];
        float e[4];
#pragma unroll
        for (int k = 0; k < 4; k++) e[k] = g_asrc[s[k] * NHEAD + head];
        uint4 h[4];
#pragma unroll
        for (int k = 0; k < 4; k++) h[k] = *(const uint4*)&g_h16[s[k] * FEAT + c0];
#pragma unroll
        for (int k = 0; k < 4; k++) {
            float ek = e[k] + adh;
            ek = ek >= 0.f ? ek : 0.2f * ek;
            float a = __expf(ek);
            den += a;
            float2 f0 = __half22float2(*(__half2*)&h[k].x);
            float2 f1 = __half22float2(*(__half2*)&h[k].y);
            float2 f2 = __half22float2(*(__half2*)&h[k].z);
            float2 f3 = __half22float2(*(__half2*)&h[k].w);
            accA.x += f0.x * a; accA.y += f0.y * a;
            accA.z += f1.x * a; accA.w += f1.y * a;
            accB.x += f2.x * a; accB.y += f2.y * a;
            accB.z += f3.x * a; accB.w += f3.y * a;
        }
    }
    for (; i < end; i++) {
        int s = g_csr[i];
        float e = g_asrc[s * NHEAD + head] + adh;
        e = e >= 0.f ? e : 0.2f * e;
        float a = __expf(e);
        den += a;
        uint4 hv = *(const uint4*)&g_h16[s * FEAT + c0];
        float2 f0 = __half22float2(*(__half2*)&hv.x);
        float2 f1 = __half22float2(*(__half2*)&hv.y);
        float2 f2 = __half22float2(*(__half2*)&hv.z);
        float2 f3 = __half22float2(*(__half2*)&hv.w);
        accA.x += f0.x * a; accA.y += f0.y * a;
        accA.z += f1.x * a; accA.w += f1.y * a;
        accB.x += f2.x * a; accB.y += f2.y * a;
        accB.z += f3.x * a; accB.w += f3.y * a;
    }

    float inv = 1.f / den;
    float4 bA = *(const float4*)&bias[c0];
    float4 bB = *(const float4*)&bias[c0 + 4];
    accA.x = fmaxf(accA.x * inv + bA.x, 0.f); accA.y = fmaxf(accA.y * inv + bA.y, 0.f);
    accA.z = fmaxf(accA.z * inv + bA.z, 0.f); accA.w = fmaxf(accA.w * inv + bA.w, 0.f);
    accB.x = fmaxf(accB.x * inv + bB.x, 0.f); accB.y = fmaxf(accB.y * inv + bB.y, 0.f);
    accB.z = fmaxf(accB.z * inv + bB.z, 0.f); accB.w = fmaxf(accB.w * inv + bB.w, 0.f);
    float sq = accA.x * accA.x + accA.y * accA.y + accA.z * accA.z + accA.w * accA.w
             + accB.x * accB.x + accB.y * accB.y + accB.z * accB.z + accB.w * accB.w;
#pragma unroll
    for (int st = 16; st >= 1; st >>= 1)
        sq += __shfl_xor_sync(0xffffffff, sq, st);
    float sc = 1.f / fmaxf(sqrtf(sq), 1e-12f);
    accA.x *= sc; accA.y *= sc; accA.z *= sc; accA.w *= sc;
    accB.x *= sc; accB.y *= sc; accB.z *= sc; accB.w *= sc;
    *(float4*)&out[w * FEAT + c0]     = accA;
    *(float4*)&out[w * FEAT + c0 + 4] = accB;
}

// ---------------- launch: fork-join over two streams ----------------
static cudaStream_t g_s2 = nullptr;
static cudaEvent_t  g_eStart = nullptr, g_eEdges = nullptr;
static bool g_streams_ok = false;

extern "C" void kernel_launch(void* const* d_in, const int* in_sizes, int n_in,
                              void* d_out, int out_size) {
    const float* x       = (const float*)d_in[0];
    const int*   ei      = (const int*)  d_in[1];
    const float* W       = (const float*)d_in[2];
    const float* att_src = (const float*)d_in[3];
    const float* att_dst = (const float*)d_in[4];
    const float* bias    = (const float*)d_in[5];
    float* out = (float*)d_out;

    const int N = in_sizes[0] / FEAT;
    const int E = in_sizes[1] / 2;
    const int tot = E + N;
    const int nb = (N + 1023) / 1024;

    static bool init_done = false;
    if (!init_done) {
        cudaFuncSetAttribute(gemm_bf16_kernel,
                             cudaFuncAttributeMaxDynamicSharedMemorySize, GEMM_SMEM_BYTES);
        bool ok = (cudaStreamCreateWithFlags(&g_s2, cudaStreamNonBlocking) == cudaSuccess);
        ok = ok && (cudaEventCreateWithFlags(&g_eStart, cudaEventDisableTiming) == cudaSuccess);
        ok = ok && (cudaEventCreateWithFlags(&g_eEdges, cudaEventDisableTiming) == cudaSuccess);
        g_streams_ok = ok;
        init_done = true;
    }

    dim3 ggrid(FEAT / 128, (N + 127) / 128);

    if (g_streams_ok) {
        zero_kernel<<<(N + 256) / 256, 256>>>(N);
        cudaEventRecord(g_eStart, 0);

        // chain B on stream 0 (gemm = issue index 3, profiled control)
        split_x_kernel<<<(N * 64 + 255) / 256, 256>>>(x, N * 64);
        split_w_kernel<<<(FEAT * FEAT / 4 + 255) / 256, 256>>>(W, FEAT * FEAT / 4);
        gemm_bf16_kernel<<<ggrid, 256, GEMM_SMEM_BYTES>>>(att_src, att_dst, N);

        // chain A on s2: count -> 3-phase scan -> scatter
        cudaStreamWaitEvent(g_s2, g_eStart, 0);
        count_kernel<<<(tot + 255) / 256, 256, 0, g_s2>>>(ei, E, N);
        scan1_kernel<<<nb, 256, 0, g_s2>>>(N);
        scan2_kernel<<<1, 64, 0, g_s2>>>(nb, N);
        scan3_kernel<<<nb, 256, 0, g_s2>>>(N);
        scatter_kernel<<<(tot + 255) / 256, 256, 0, g_s2>>>(ei, E, N);
        cudaEventRecord(g_eEdges, g_s2);

        cudaStreamWaitEvent(0, g_eEdges, 0);
        aggregate_kernel<<<(N * 32 + 63) / 64, 64>>>(bias, out, N);
    } else {
        zero_kernel<<<(N + 256) / 256, 256>>>(N);
        split_x_kernel<<<(N * 64 + 255) / 256, 256>>>(x, N * 64);
        split_w_kernel<<<(FEAT * FEAT / 4 + 255) / 256, 256>>>(W, FEAT * FEAT / 4);
        gemm_bf16_kernel<<<ggrid, 256, GEMM_SMEM_BYTES>>>(att_src, att_dst, N);
        count_kernel<<<(tot + 255) / 256, 256>>>(ei, E, N);
        scan1_kernel<<<nb, 256>>>(N);
        scan2_kernel<<<1, 64>>>(nb, N);
        scan3_kernel<<<nb, 256>>>(N);
        scatter_kernel<<<(tot + 255) / 256, 256>>>(ei, E, N);
        aggregate_kernel<<<(N * 32 + 63) / 64, 64>>>(bias, out, N);
    }
}